// round 17
// baseline (speedup 1.0000x reference)
#include <cuda_runtime.h>
#include <cuda_fp16.h>
#include <stdint.h>

#define N_NODES_MAX 100000
#define N_EDGES_MAX 1250000
#define D_FEAT 64
#define BLK 256
#define GRID_B 592   // 4 blocks/SM x 148 SMs -> guaranteed co-resident (GB300 has 152)

// ---- static scratch (no cudaMalloc allowed) ----
__device__ __half g_xh[(size_t)N_NODES_MAX * D_FEAT];    // x in fp16
__device__ __half g_th[(size_t)N_NODES_MAX * D_FEAT];    // relu(conv1) in fp16
__device__ int    g_deg[N_NODES_MAX];
__device__ int    g_rowptr[N_NODES_MAX + 4];
__device__ int    g_rank[N_EDGES_MAX];
__device__ int    g_src_sorted[N_EDGES_MAX];
__device__ int    g_blocksums[(N_NODES_MAX + BLK - 1) / BLK + 1];   // per 256-tile
__device__ int    g_idx_is64;
__device__ int    g_bar_count;
__device__ volatile int g_bar_gen;

// ---- device-wide barrier: generation-based, safe across graph replays ----
__device__ __forceinline__ void grid_barrier() {
    __syncthreads();
    if (threadIdx.x == 0) {
        __threadfence();
        int gen = g_bar_gen;                  // read BEFORE arriving
        if (atomicAdd(&g_bar_count, 1) == (int)gridDim.x - 1) {
            atomicExch(&g_bar_count, 0);
            __threadfence();
            g_bar_gen = gen + 1;
        } else {
            while (g_bar_gen == gen) {}
        }
        __threadfence();
    }
    __syncthreads();
}

__global__ void __launch_bounds__(BLK, 4)
mega_kernel(const float* __restrict__ x, const void* __restrict__ ei,
            float* __restrict__ out, int n_nodes, int n_edges, int n_floats) {
    int tid = threadIdx.x;
    int bid = blockIdx.x;
    int gtid = bid * BLK + tid;
    int gsz = gridDim.x * BLK;

    // ================= Phase A: dtype probe + zero deg =================
    if (bid == 0) {
        int nz = 0;
        const unsigned int* w = (const unsigned int*)ei;
        #pragma unroll
        for (int k = 0; k < 4; ++k) {
            int i = tid * 4 + k;   // first 1024 "int64" entries (n_edges >> 1024)
            if (w[2 * i + 1] != 0u) nz = 1;
        }
        int any = __syncthreads_or(nz);
        if (tid == 0) g_idx_is64 = any ? 0 : 1;
    }
    for (int i = gtid; i < n_nodes; i += gsz) g_deg[i] = 0;
    grid_barrier();

    // ================= Phase B: histogram(+rank) AND fp16 convert =================
    int is64 = g_idx_is64;
    if (!is64) {
        const int* dst = ((const int*)ei) + n_edges;
        int n_vec = n_edges >> 2;
        for (int c = gtid; c < n_vec; c += gsz) {
            int4 d = __ldg(((const int4*)dst) + c);
            int4 r;
            r.x = atomicAdd(&g_deg[d.x], 1);
            r.y = atomicAdd(&g_deg[d.y], 1);
            r.z = atomicAdd(&g_deg[d.z], 1);
            r.w = atomicAdd(&g_deg[d.w], 1);
            *reinterpret_cast<int4*>(g_rank + c * 4) = r;
        }
        if (gtid == 0) {
            for (int e = n_vec * 4; e < n_edges; ++e)
                g_rank[e] = atomicAdd(&g_deg[__ldg(dst + e)], 1);
        }
    } else {
        const long long* dst = ((const long long*)ei) + n_edges;
        for (int e = gtid; e < n_edges; e += gsz)
            g_rank[e] = atomicAdd(&g_deg[(int)__ldg(dst + e)], 1);
    }
    // convert x -> fp16 (independent of hist; overlapped in this phase)
    {
        int n8 = n_floats >> 3;
        for (int i = gtid; i < n8; i += gsz) {
            int base = i * 8;
            float4 a = *reinterpret_cast<const float4*>(x + base);
            float4 c = *reinterpret_cast<const float4*>(x + base + 4);
            __half2 h[4];
            h[0] = __floats2half2_rn(a.x, a.y);
            h[1] = __floats2half2_rn(a.z, a.w);
            h[2] = __floats2half2_rn(c.x, c.y);
            h[3] = __floats2half2_rn(c.z, c.w);
            *reinterpret_cast<uint4*>(g_xh + base) = *reinterpret_cast<uint4*>(h);
        }
        if (gtid == 0) {
            for (int k = (n_floats >> 3) << 3; k < n_floats; ++k)
                g_xh[k] = __float2half_rn(x[k]);
        }
    }
    grid_barrier();

    // ================= Phase C1: per-tile (256) scan -> rowptr + blocksums =================
    int nb_tiles = (n_nodes + BLK - 1) / BLK;
    __shared__ int s_warp[8];
    __shared__ int s_off;
    for (int tile = bid; tile < nb_tiles; tile += gridDim.x) {
        int i = tile * BLK + tid;
        int v = (i < n_nodes) ? g_deg[i] : 0;
        int lane = tid & 31, wd = tid >> 5;
        int incl = v;
        #pragma unroll
        for (int off = 1; off < 32; off <<= 1) {
            int u = __shfl_up_sync(0xffffffffu, incl, off);
            if (lane >= off) incl += u;
        }
        if (lane == 31) s_warp[wd] = incl;
        __syncthreads();
        if (wd == 0) {
            int ws = (lane < 8) ? s_warp[lane] : 0;
            int wincl = ws;
            #pragma unroll
            for (int off = 1; off < 8; off <<= 1) {
                int u = __shfl_up_sync(0xffffffffu, wincl, off);
                if (lane >= off) wincl += u;
            }
            if (lane < 8) s_warp[lane] = wincl - ws;   // exclusive warp offsets
            if (lane == 7) g_blocksums[tile] = wincl;  // tile total
        }
        __syncthreads();
        if (i < n_nodes) g_rowptr[i] = incl - v + s_warp[wd];
        __syncthreads();
    }
    grid_barrier();

    // ================= Phase C2: lookback offsets =================
    for (int tile = bid; tile < nb_tiles; tile += gridDim.x) {
        if (tid < 32) {
            int a = 0;
            for (int p = tid; p < tile; p += 32) a += __ldg(g_blocksums + p);
            #pragma unroll
            for (int off = 16; off > 0; off >>= 1)
                a += __shfl_down_sync(0xffffffffu, a, off);
            if (tid == 0) s_off = a;
        }
        __syncthreads();
        int i = tile * BLK + tid;
        if (i < n_nodes) g_rowptr[i] += s_off;
        __syncthreads();
    }
    if (gtid == 0) g_rowptr[n_nodes] = n_edges;
    grid_barrier();

    // ================= Phase D: fill dst-sorted src list (atomic-free) =================
    if (!is64) {
        const int* srcp = (const int*)ei;
        const int* dstp = srcp + n_edges;
        int n_vec = n_edges >> 2;
        for (int c = gtid; c < n_vec; c += gsz) {
            int4 s = __ldg(((const int4*)srcp) + c);
            int4 d = __ldg(((const int4*)dstp) + c);
            int4 r = __ldg(((const int4*)g_rank) + c);
            int p0 = __ldg(g_rowptr + d.x);
            int p1 = __ldg(g_rowptr + d.y);
            int p2 = __ldg(g_rowptr + d.z);
            int p3 = __ldg(g_rowptr + d.w);
            g_src_sorted[p0 + r.x] = s.x;
            g_src_sorted[p1 + r.y] = s.y;
            g_src_sorted[p2 + r.z] = s.z;
            g_src_sorted[p3 + r.w] = s.w;
        }
        if (gtid == 0) {
            for (int e = n_vec * 4; e < n_edges; ++e)
                g_src_sorted[__ldg(g_rowptr + __ldg(dstp + e)) + __ldg(g_rank + e)] = __ldg(srcp + e);
        }
    } else {
        const long long* srcp = (const long long*)ei;
        for (int e = gtid; e < n_edges; e += gsz) {
            int s = (int)__ldg(srcp + e);
            int dd = (int)__ldg(srcp + n_edges + e);
            g_src_sorted[__ldg(g_rowptr + dd) + __ldg(g_rank + e)] = s;
        }
    }
    grid_barrier();

    // ================= Phase E: agg1 tmp = relu(sum xh[src]) =================
    {
        int slot = gtid >> 3;
        int lane = tid & 7;
        int nslots = gsz >> 3;
        for (int node = slot; node < n_nodes; node += nslots) {
            int beg = __ldg(g_rowptr + node);
            int end = __ldg(g_rowptr + node + 1);
            float acc[8];
            #pragma unroll
            for (int k = 0; k < 8; ++k) acc[k] = 0.f;
            int j = beg;
            for (; j + 1 < end; j += 2) {
                int s0 = __ldg(g_src_sorted + j);
                int s1 = __ldg(g_src_sorted + j + 1);
                uint4 a = __ldg((const uint4*)(g_xh + (size_t)s0 * D_FEAT) + lane);
                uint4 b = __ldg((const uint4*)(g_xh + (size_t)s1 * D_FEAT) + lane);
                const __half2* ha = (const __half2*)&a;
                const __half2* hb = (const __half2*)&b;
                #pragma unroll
                for (int k = 0; k < 4; ++k) {
                    float2 fa = __half22float2(ha[k]);
                    float2 fb = __half22float2(hb[k]);
                    acc[2 * k]     += fa.x + fb.x;
                    acc[2 * k + 1] += fa.y + fb.y;
                }
            }
            if (j < end) {
                int s = __ldg(g_src_sorted + j);
                uint4 a = __ldg((const uint4*)(g_xh + (size_t)s * D_FEAT) + lane);
                const __half2* ha = (const __half2*)&a;
                #pragma unroll
                for (int k = 0; k < 4; ++k) {
                    float2 fa = __half22float2(ha[k]);
                    acc[2 * k]     += fa.x;
                    acc[2 * k + 1] += fa.y;
                }
            }
            __half2 r[4];
            #pragma unroll
            for (int k = 0; k < 4; ++k)
                r[k] = __floats2half2_rn(fmaxf(acc[2 * k], 0.f), fmaxf(acc[2 * k + 1], 0.f));
            *reinterpret_cast<uint4*>(g_th + (size_t)node * D_FEAT + lane * 8) =
                *reinterpret_cast<uint4*>(r);
        }
    }
    grid_barrier();

    // ================= Phase F: agg2 out = sum th[src] (fp32) =================
    {
        int slot = gtid >> 3;
        int lane = tid & 7;
        int nslots = gsz >> 3;
        for (int node = slot; node < n_nodes; node += nslots) {
            int beg = __ldg(g_rowptr + node);
            int end = __ldg(g_rowptr + node + 1);
            float acc[8];
            #pragma unroll
            for (int k = 0; k < 8; ++k) acc[k] = 0.f;
            int j = beg;
            for (; j + 1 < end; j += 2) {
                int s0 = __ldg(g_src_sorted + j);
                int s1 = __ldg(g_src_sorted + j + 1);
                uint4 a = __ldg((const uint4*)(g_th + (size_t)s0 * D_FEAT) + lane);
                uint4 b = __ldg((const uint4*)(g_th + (size_t)s1 * D_FEAT) + lane);
                const __half2* ha = (const __half2*)&a;
                const __half2* hb = (const __half2*)&b;
                #pragma unroll
                for (int k = 0; k < 4; ++k) {
                    float2 fa = __half22float2(ha[k]);
                    float2 fb = __half22float2(hb[k]);
                    acc[2 * k]     += fa.x + fb.x;
                    acc[2 * k + 1] += fa.y + fb.y;
                }
            }
            if (j < end) {
                int s = __ldg(g_src_sorted + j);
                uint4 a = __ldg((const uint4*)(g_th + (size_t)s * D_FEAT) + lane);
                const __half2* ha = (const __half2*)&a;
                #pragma unroll
                for (int k = 0; k < 4; ++k) {
                    float2 fa = __half22float2(ha[k]);
                    acc[2 * k]     += fa.x;
                    acc[2 * k + 1] += fa.y;
                }
            }
            float* op = out + (size_t)node * D_FEAT + lane * 8;
            *reinterpret_cast<float4*>(op)     = make_float4(acc[0], acc[1], acc[2], acc[3]);
            *reinterpret_cast<float4*>(op + 4) = make_float4(acc[4], acc[5], acc[6], acc[7]);
        }
    }
}

extern "C" void kernel_launch(void* const* d_in, const int* in_sizes, int n_in,
                              void* d_out, int out_size) {
    const float* x = (const float*)d_in[0];   // [N_NODES, 64] f32
    const void* ei = d_in[1];                 // [2, N_EDGES] i64 or i32

    int n_edges = in_sizes[1] / 2;
    if (n_edges > N_EDGES_MAX) n_edges = N_EDGES_MAX;
    int n_nodes = in_sizes[0] / D_FEAT;
    if (n_nodes > N_NODES_MAX) n_nodes = N_NODES_MAX;
    int n_node_floats = in_sizes[0];

    mega_kernel<<<GRID_B, BLK>>>(x, ei, (float*)d_out, n_nodes, n_edges, n_node_floats);
}